// round 7
// baseline (speedup 1.0000x reference)
#include <cuda_runtime.h>
#include <cuda_bf16.h>
#include <math.h>
#include <stdint.h>

// ---------------------------------------------------------------------------
// HPNETLoss — fused kernel with cp.async.bulk (TMA) 4-stage SMEM pipeline for
// the 201 MB streaming reduction, replacing per-thread LDG with bulk-async.
//   out[0] = sum(weight * (confidence - confidence_gt)^2) / 65536   (16.7M)
//   out[1] = sum(mask * (dr[:,0]-ann[:,0])^2) / N                   (N=8192)
//   out[2] = sum(mask * min(||Mgt-Mp||F, ||Mgt-Mp@RY||F)) / N
// ---------------------------------------------------------------------------

#define BT 256
#define GB 128                    // 1 block/SM on 128 SMs; 4096 tiles / 128 = 32 each
#define NSTAGE 4
#define TILE_ELEMS 4096           // floats per array per tile
#define TILE_BYTES (TILE_ELEMS * 4)          // 16 KB
#define STAGE_BYTES (3 * TILE_BYTES)         // 48 KB (conf+gt+wgt)
#define DYN_SMEM (NSTAGE * STAGE_BYTES)      // 192 KB

__device__ float        g_scratch[3];   // self-resetting accumulators
__device__ unsigned int g_count;        // wraps to 0 via atomicInc

// ---- minimal PTX helpers ---------------------------------------------------
__device__ __forceinline__ uint32_t s2u(const void* p) {
    uint32_t a;
    asm("{ .reg .u64 t; cvta.to.shared.u64 t, %1; cvt.u32.u64 %0, t; }"
        : "=r"(a) : "l"(p));
    return a;
}
__device__ __forceinline__ void mb_init(uint32_t a, uint32_t c) {
    asm volatile("mbarrier.init.shared.b64 [%0], %1;" :: "r"(a), "r"(c) : "memory");
}
__device__ __forceinline__ void mb_expect(uint32_t a, uint32_t bytes) {
    asm volatile("mbarrier.arrive.expect_tx.shared.b64 _, [%0], %1;"
                 :: "r"(a), "r"(bytes) : "memory");
}
__device__ __forceinline__ void mb_arrive(uint32_t a) {
    asm volatile("mbarrier.arrive.shared.b64 _, [%0];" :: "r"(a) : "memory");
}
__device__ __forceinline__ void mb_wait(uint32_t a, uint32_t parity) {
    uint32_t done;
    asm volatile(
        "{ .reg .pred p; mbarrier.try_wait.parity.acquire.cta.shared::cta.b64 p, [%1], %2;"
        " selp.b32 %0, 1, 0, p; }"
        : "=r"(done) : "r"(a), "r"(parity) : "memory");
    if (!done) {
        asm volatile(
            "{ .reg .pred P;\n"
            "WL_%=: mbarrier.try_wait.parity.acquire.cta.shared::cta.b64 P, [%0], %1, 0x989680;\n"
            "@P bra WD_%=;\n"
            "bra WL_%=;\n"
            "WD_%=: }"
            :: "r"(a), "r"(parity) : "memory");
    }
}
__device__ __forceinline__ void bulk_g2s(uint32_t dst, const void* src,
                                         uint32_t bytes, uint32_t mbar) {
    asm volatile(
        "cp.async.bulk.shared::cta.global.mbarrier::complete_tx::bytes [%0], [%1], %2, [%3];"
        :: "r"(dst), "l"(src), "r"(bytes), "r"(mbar) : "memory");
}
__device__ __forceinline__ void fence_proxy_async_cta() {
    asm volatile("fence.proxy.async.shared::cta;" ::: "memory");
}
// ---------------------------------------------------------------------------

__device__ __forceinline__ float block_reduce(float v, float* warp_sums) {
    int lane = threadIdx.x & 31;
    int wid  = threadIdx.x >> 5;
    #pragma unroll
    for (int off = 16; off > 0; off >>= 1)
        v += __shfl_down_sync(0xFFFFFFFFu, v, off);
    if (lane == 0) warp_sums[wid] = v;
    __syncthreads();
    v = (threadIdx.x < (BT / 32)) ? warp_sums[threadIdx.x] : 0.0f;
    if (wid == 0) {
        #pragma unroll
        for (int off = 16; off > 0; off >>= 1)
            v += __shfl_down_sync(0xFFFFFFFFu, v, off);
    }
    __syncthreads();
    return v;
}

__device__ __forceinline__ void quat2mat(float q0, float q1, float q2, float q3,
                                         float m[9]) {
    m[0] = q0*q0 + q1*q1 - q2*q2 - q3*q3;
    m[1] = 2.0f * (q1*q2 - q0*q3);
    m[2] = 2.0f * (q1*q3 + q0*q2);
    m[3] = 2.0f * (q1*q2 + q0*q3);
    m[4] = q0*q0 - q1*q1 + q2*q2 - q3*q3;
    m[5] = 2.0f * (q2*q3 - q0*q1);
    m[6] = 2.0f * (q1*q3 - q0*q2);
    m[7] = 2.0f * (q2*q3 + q0*q1);
    m[8] = q0*q0 - q1*q1 - q2*q2 + q3*q3;
}

__device__ __forceinline__ float wsq4(float4 w, float4 c, float4 g, float acc) {
    float d0 = c.x - g.x;
    float d1 = c.y - g.y;
    float d2 = c.z - g.z;
    float d3 = c.w - g.w;
    acc = fmaf(w.x * d0, d0, acc);
    acc = fmaf(w.y * d1, d1, acc);
    acc = fmaf(w.z * d2, d2, acc);
    acc = fmaf(w.w * d3, d3, acc);
    return acc;
}

extern __shared__ char dyn_smem[];

__global__ __launch_bounds__(BT)
void hpnet_loss_tma(const float* __restrict__ conf,
                    const float* __restrict__ gt,
                    const float* __restrict__ wgt,
                    const float* __restrict__ dr,
                    const float* __restrict__ ann,
                    const int*   __restrict__ flags,
                    float* __restrict__ out,
                    unsigned n, int N) {
    __shared__ float warp_sums[BT / 32];
    __shared__ uint64_t mbar_full[NSTAGE];
    __shared__ uint64_t mbar_empty[NSTAGE];

    const int tid = threadIdx.x;
    const int bid = blockIdx.x;
    const unsigned gid = bid * BT + tid;

    // ---- init pipeline barriers
    if (tid == 0) {
        #pragma unroll
        for (int s = 0; s < NSTAGE; ++s) {
            mb_init(s2u(&mbar_full[s]), 1);      // completed by TMA tx bytes
            mb_init(s2u(&mbar_empty[s]), BT);    // all threads arrive after consume
        }
        fence_proxy_async_cta();
    }
    __syncthreads();

    // ---- ann loss (small; done while first TMA tiles are in flight)
    float dpart = 0.0f, rpart = 0.0f;
    for (unsigned i = gid; i < (unsigned)N; i += GB * BT) {
        if (flags[i] != 0) {
            float dd = dr[i*5 + 0] - ann[i*5 + 0];
            dpart += dd * dd;

            float mp[9];
            quat2mat(ann[i*5+1], ann[i*5+2], ann[i*5+3], ann[i*5+4], mp);

            float q0 = dr[i*5+1], q1 = dr[i*5+2], q2 = dr[i*5+3], q3 = dr[i*5+4];
            float inv = rsqrtf(q0*q0 + q1*q1 + q2*q2 + q3*q3);
            float mg[9];
            quat2mat(q0*inv, q1*inv, q2*inv, q3*inv, mg);

            // RY = diag(-1,1,-1): columns 0,2 of mp negated for the second norm
            float s1 = 0.0f, s2 = 0.0f;
            #pragma unroll
            for (int r = 0; r < 3; ++r) {
                float e0 = mg[r*3+0] - mp[r*3+0];
                float e1 = mg[r*3+1] - mp[r*3+1];
                float e2 = mg[r*3+2] - mp[r*3+2];
                s1 += e0*e0 + e1*e1 + e2*e2;
                float f0 = mg[r*3+0] + mp[r*3+0];
                float f1 = mg[r*3+1] - mp[r*3+1];
                float f2 = mg[r*3+2] + mp[r*3+2];
                s2 += f0*f0 + f1*f1 + f2*f2;
            }
            rpart += sqrtf(fminf(s1, s2));
        }
    }

    // ---- confidence loss: 4-stage bulk-async pipeline
    const unsigned tiles_total = n / TILE_ELEMS;                     // 4096
    const unsigned nt = (tiles_total > (unsigned)bid)
                      ? (tiles_total - bid + GB - 1) / GB : 0;       // 32 each

    float acc = 0.0f;
    unsigned issued = 0;

    for (unsigned consumed = 0; consumed < nt; ++consumed) {
        // producer (thread 0): top up lookahead
        if (tid == 0) {
            while (issued < nt && issued < consumed + NSTAGE) {
                unsigned s = issued & (NSTAGE - 1);
                if (issued >= NSTAGE)
                    mb_wait(s2u(&mbar_empty[s]), ((issued - NSTAGE) >> 2) & 1);
                uint32_t fb = s2u(&mbar_full[s]);
                mb_expect(fb, STAGE_BYTES);
                size_t off = (size_t)(bid + issued * GB) * TILE_ELEMS;
                uint32_t base = s2u(dyn_smem) + s * STAGE_BYTES;
                bulk_g2s(base,                  conf + off, TILE_BYTES, fb);
                bulk_g2s(base + TILE_BYTES,     gt   + off, TILE_BYTES, fb);
                bulk_g2s(base + 2*TILE_BYTES,   wgt  + off, TILE_BYTES, fb);
                ++issued;
            }
        }

        // consumer: wait for this stage, reduce the tile from SMEM
        unsigned s = consumed & (NSTAGE - 1);
        mb_wait(s2u(&mbar_full[s]), (consumed >> 2) & 1);

        const float4* cb = (const float4*)(dyn_smem + s * STAGE_BYTES);
        const float4* gb = (const float4*)(dyn_smem + s * STAGE_BYTES + TILE_BYTES);
        const float4* wb = (const float4*)(dyn_smem + s * STAGE_BYTES + 2*TILE_BYTES);
        #pragma unroll
        for (int k = 0; k < TILE_ELEMS / 4 / BT; ++k) {
            int idx = tid + k * BT;
            acc = wsq4(wb[idx], cb[idx], gb[idx], acc);
        }
        mb_arrive(s2u(&mbar_empty[s]));
    }

    // remainder elements (none when n is a multiple of TILE_ELEMS): block 0 only
    unsigned rem_start = tiles_total * TILE_ELEMS;
    if (bid == 0) {
        for (unsigned i = rem_start + tid; i < n; i += BT) {
            float d = conf[i] - gt[i];
            acc = fmaf(wgt[i] * d, d, acc);
        }
    }

    // ---- block reductions + completion
    float csum = block_reduce(acc,   warp_sums);
    float dsum = block_reduce(dpart, warp_sums);
    float rsum = block_reduce(rpart, warp_sums);

    if (tid == 0) {
        if (csum != 0.0f) atomicAdd(&g_scratch[0], csum);
        if (dsum != 0.0f) atomicAdd(&g_scratch[1], dsum);
        if (rsum != 0.0f) atomicAdd(&g_scratch[2], rsum);
        __threadfence();
        unsigned int ticket = atomicInc(&g_count, GB - 1);
        if (ticket == GB - 1) {
            float s0 = atomicExch(&g_scratch[0], 0.0f);
            float s1 = atomicExch(&g_scratch[1], 0.0f);
            float s2 = atomicExch(&g_scratch[2], 0.0f);
            float invN = 1.0f / (float)N;
            out[0] = s0 * (1.0f / 65536.0f);
            out[1] = s1 * invN;
            out[2] = s2 * invN;
        }
    }
}

extern "C" void kernel_launch(void* const* d_in, const int* in_sizes, int n_in,
                              void* d_out, int out_size) {
    const float* conf = (const float*)d_in[0];
    const float* gt   = (const float*)d_in[1];
    const float* wgt  = (const float*)d_in[2];
    const float* dr   = (const float*)d_in[3];
    const float* ann  = (const float*)d_in[4];
    const int*   flags = (const int*)d_in[5];
    float* out = (float*)d_out;

    unsigned n = (unsigned)in_sizes[0];   // 16,777,216
    int N = in_sizes[5];                  // 8192

    static int smem_set = 0;
    if (!smem_set) {
        cudaFuncSetAttribute(hpnet_loss_tma,
                             cudaFuncAttributeMaxDynamicSharedMemorySize, DYN_SMEM);
        smem_set = 1;
    }

    hpnet_loss_tma<<<GB, BT, DYN_SMEM>>>(conf, gt, wgt, dr, ann, flags, out, n, N);
}